// round 12
// baseline (speedup 1.0000x reference)
#include <cuda_runtime.h>
#include <cstdint>

// Problem shape (fixed)
#define BB 2
#define SS 2048
#define EE 1024
#define HH 16
#define DD 64
#define MTOT (BB*SS)   // 4096

// Scratch (device globals)
__device__ float g_xr[MTOT*EE];        // x rounded to tf32 grid
__device__ float g_wt[3*EE*EE];        // W{q,k,v}^T: [which][n=h*64+d][e], rna-rounded
__device__ float g_wpt[EE*EE];         // Wp^T: [n][k], rna-rounded
__device__ float g_q[BB*HH*SS*DD];     // [B,H,S,D], rna-rounded
__device__ float g_k[BB*HH*SS*DD];
__device__ float g_v[BB*HH*SS*DD];
__device__ float g_attn[BB*SS*HH*DD];  // [B,S,H*D], rna-rounded

// ============================ helpers ============================
__device__ __forceinline__ uint32_t smem_to_u32(const void* p) {
    uint32_t a;
    asm("{ .reg .u64 t; cvta.to.shared.u64 t, %1; cvt.u32.u64 %0, t; }" : "=r"(a) : "l"(p));
    return a;
}
__device__ __forceinline__ float rna_tf32(float v) {
    float r; asm("cvt.rna.tf32.f32 %0, %1;" : "=f"(r) : "f"(v)); return r;
}
__device__ __forceinline__ void ldgsts16(uint32_t s, const float* g) {
    asm volatile("cp.async.cg.shared.global [%0], [%1], 16;" :: "r"(s), "l"(g) : "memory");
}
#define CP_COMMIT() asm volatile("cp.async.commit_group;" ::: "memory")
#define CP_WAIT2()  asm volatile("cp.async.wait_group 2;" ::: "memory")

// m16n8k8 tf32 mma: D += A*B   (fragment conventions validated in R5/R6)
__device__ __forceinline__ void mma16n8k8(float* d, const uint32_t* a, const uint32_t* b) {
    asm volatile(
        "mma.sync.aligned.m16n8k8.row.col.f32.tf32.tf32.f32 "
        "{%0,%1,%2,%3}, {%4,%5,%6,%7}, {%8,%9}, {%0,%1,%2,%3};\n"
        : "+f"(d[0]), "+f"(d[1]), "+f"(d[2]), "+f"(d[3])
        : "r"(a[0]), "r"(a[1]), "r"(a[2]), "r"(a[3]), "r"(b[0]), "r"(b[1]));
}

// ldmatrix x4: four 8-row x 16B matrices; lane groups 0-7/8-15/16-23/24-31
// supply row addresses for matrices 0..3 -> dest regs r[0..3].
__device__ __forceinline__ void ldm_x4(uint32_t* r, uint32_t addr) {
    asm volatile("ldmatrix.sync.aligned.m8n8.x4.shared.b16 {%0,%1,%2,%3}, [%4];"
        : "=r"(r[0]), "=r"(r[1]), "=r"(r[2]), "=r"(r[3]) : "r"(addr));
}

// ============================ prep kernels ============================
__global__ __launch_bounds__(256) void round_x_kernel(const float* __restrict__ x)
{
    int i = blockIdx.x * blockDim.x + threadIdx.x;
    const int n4 = MTOT * EE / 4;
    for (; i < n4; i += gridDim.x * blockDim.x) {
        float4 v = ((const float4*)x)[i];
        v.x = rna_tf32(v.x); v.y = rna_tf32(v.y);
        v.z = rna_tf32(v.z); v.w = rna_tf32(v.w);
        ((float4*)g_xr)[i] = v;
    }
}

__global__ __launch_bounds__(256) void transpose_w_kernel(
    const float* __restrict__ Wq, const float* __restrict__ Wk, const float* __restrict__ Wv)
{
    __shared__ float t[32][33];
    const int zc = blockIdx.z;              // 0..47
    const int which = zc >> 4, h = zc & 15;
    const float* W = ((which == 0) ? Wq : (which == 1) ? Wk : Wv) + (size_t)h * EE * DD;
    const int e0 = blockIdx.x * 32, d0 = blockIdx.y * 32;
    const int tx = threadIdx.x & 31, ty8 = threadIdx.x >> 5;
    #pragma unroll
    for (int i = 0; i < 4; i++) {
        int e = ty8 + i * 8;
        t[e][tx] = rna_tf32(W[(size_t)(e0 + e) * DD + d0 + tx]);
    }
    __syncthreads();
    float* dst = g_wt + (size_t)which * EE * EE;
    #pragma unroll
    for (int i = 0; i < 4; i++) {
        int dr = ty8 + i * 8;
        dst[(size_t)(h * DD + d0 + dr) * EE + e0 + tx] = t[tx][dr];
    }
}

__global__ __launch_bounds__(256) void transpose_wp_kernel(const float* __restrict__ Wp)
{
    __shared__ float t[32][33];
    const int k0 = blockIdx.x * 32, n0 = blockIdx.y * 32;
    const int tx = threadIdx.x & 31, ty8 = threadIdx.x >> 5;
    #pragma unroll
    for (int i = 0; i < 4; i++) {
        int k = ty8 + i * 8;
        t[k][tx] = rna_tf32(Wp[(size_t)(k0 + k) * EE + n0 + tx]);
    }
    __syncthreads();
    #pragma unroll
    for (int i = 0; i < 4; i++) {
        int nr = ty8 + i * 8;
        g_wpt[(size_t)(n0 + nr) * EE + k0 + tx] = t[tx][nr];
    }
}

// ============================ mma.sync GEMM core ============================
// 4-stage cp.async pipeline, one __syncthreads per k-tile; ldmatrix fragments.
// (R9+R10, passed — unchanged.)
#define PITCH   20
#define STAGE_F (2*128*PITCH)      // 5120 floats per stage
#define GSMEM_BYTES (4*STAGE_F*4)  // 81920

__device__ __forceinline__ void gemm_load_stage(
    uint32_t smem_u32, int s, const float* __restrict__ Ag, const float* __restrict__ Bg,
    int m0, int n0, int kt, int tid)
{
    const uint32_t baseA = smem_u32 + s * (STAGE_F * 4);
    const uint32_t baseB = baseA + 128 * PITCH * 4;
    #pragma unroll
    for (int i = 0; i < 2; i++) {
        int cid = tid + i * 256;
        int r = cid >> 2, c = cid & 3;
        ldgsts16(baseA + (r * PITCH + c * 4) * 4, Ag + (size_t)(m0 + r) * EE + kt * 16 + c * 4);
        ldgsts16(baseB + (r * PITCH + c * 4) * 4, Bg + (size_t)(n0 + r) * EE + kt * 16 + c * 4);
    }
    CP_COMMIT();
}

__device__ __forceinline__ void gemm_mainloop_mma(
    const float* __restrict__ Ag, const float* __restrict__ Bg,
    int m0, int n0, float acc[2][8][4], float* __restrict__ sm)
{
    const int tid  = threadIdx.x;
    const int lane = tid & 31, wid = tid >> 5;
    const int wm = wid & 3, wn = wid >> 2;
    const uint32_t smem_u32 = smem_to_u32(sm);

    const int Lq = lane & 7, grp = lane >> 3;
    const int offA = (wm * 32 + (grp & 1) * 8 + Lq) * PITCH + (grp >> 1) * 4;
    const int offB = (wn * 64 + (grp >> 1) * 8 + Lq) * PITCH + (grp & 1) * 4;

    gemm_load_stage(smem_u32, 0, Ag, Bg, m0, n0, 0, tid);
    gemm_load_stage(smem_u32, 1, Ag, Bg, m0, n0, 1, tid);
    gemm_load_stage(smem_u32, 2, Ag, Bg, m0, n0, 2, tid);

    const int KT = EE / 16;   // 64
    for (int t = 0; t < KT; t++) {
        const int s = t & 3;
        CP_WAIT2();
        __syncthreads();

        if (t + 3 < KT) gemm_load_stage(smem_u32, (t + 3) & 3, Ag, Bg, m0, n0, t + 3, tid);
        else            CP_COMMIT();

        const uint32_t aBase = smem_u32 + s * (STAGE_F * 4);
        const uint32_t bBase = aBase + 128 * PITCH * 4;
        #pragma unroll
        for (int ks = 0; ks < 16; ks += 8) {
            uint32_t af[2][4], bf[8][2];
            ldm_x4(af[0], aBase + (offA + ks) * 4);
            ldm_x4(af[1], aBase + (offA + 16 * PITCH + ks) * 4);
            #pragma unroll
            for (int ntp = 0; ntp < 4; ntp++) {
                uint32_t tb[4];
                ldm_x4(tb, bBase + (offB + ntp * 16 * PITCH + ks) * 4);
                bf[2 * ntp][0] = tb[0]; bf[2 * ntp][1] = tb[1];
                bf[2 * ntp + 1][0] = tb[2]; bf[2 * ntp + 1][1] = tb[3];
            }
            #pragma unroll
            for (int mt = 0; mt < 2; mt++)
                #pragma unroll
                for (int nt = 0; nt < 8; nt++)
                    mma16n8k8(acc[mt][nt], af[mt], bf[nt]);
        }
    }
}

// ---------------------------------------------------------------------------
// QKV projection: scatter + bias into g_q/g_k/g_v (rna-rounded for attn mma).
// ---------------------------------------------------------------------------
__global__ __launch_bounds__(256) void gemm_proj_kernel(
    const float* __restrict__ bq, const float* __restrict__ bk, const float* __restrict__ bv)
{
    extern __shared__ __align__(16) float sm[];
    const int n0 = blockIdx.x * 128;
    const int m0 = blockIdx.y * 128;

    float acc[2][8][4] = {};
    gemm_mainloop_mma(g_xr, g_wt, m0, n0, acc, sm);

    const int which = n0 >> 10;
    const int h0 = (n0 & 1023) >> 6;
    const float* bias = (which == 0) ? bq : (which == 1) ? bk : bv;
    float*       outp = (which == 0) ? g_q : (which == 1) ? g_k : g_v;

    const int lane = threadIdx.x & 31, wid = threadIdx.x >> 5;
    const int g = lane >> 2, t4 = lane & 3;
    const int wm = wid & 3, wn = wid >> 2;
    const int hh = h0 + wn;

    #pragma unroll
    for (int mt = 0; mt < 2; mt++) {
        #pragma unroll
        for (int half = 0; half < 2; half++) {
            const int row = m0 + wm * 32 + mt * 16 + g + half * 8;
            const int bi = row >> 11, sidx = row & (SS - 1);
            float* dst = &outp[(((size_t)(bi * HH + hh)) * SS + sidx) * DD];
            #pragma unroll
            for (int nt = 0; nt < 8; nt++) {
                const int d = nt * 8 + t4 * 2;
                float2 rv;
                rv.x = rna_tf32(acc[mt][nt][half * 2 + 0] + bias[hh * DD + d + 0]);
                rv.y = rna_tf32(acc[mt][nt][half * 2 + 1] + bias[hh * DD + d + 1]);
                *(float2*)&dst[d] = rv;
            }
        }
    }
}

// ---------------------------------------------------------------------------
// Output projection: out = relu(g_attn @ g_wpt^T + bp)
// ---------------------------------------------------------------------------
__global__ __launch_bounds__(256) void gemm_out_kernel(
    const float* __restrict__ bp, float* __restrict__ out)
{
    extern __shared__ __align__(16) float sm[];
    const int n0 = blockIdx.x * 128;
    const int m0 = blockIdx.y * 128;

    float acc[2][8][4] = {};
    gemm_mainloop_mma(g_attn, g_wpt, m0, n0, acc, sm);

    const int lane = threadIdx.x & 31, wid = threadIdx.x >> 5;
    const int g = lane >> 2, t4 = lane & 3;
    const int wm = wid & 3, wn = wid >> 2;

    #pragma unroll
    for (int mt = 0; mt < 2; mt++) {
        #pragma unroll
        for (int half = 0; half < 2; half++) {
            const int row = m0 + wm * 32 + mt * 16 + g + half * 8;
            float* dst = &out[(size_t)row * EE + n0 + wn * 64];
            const float* bptr = &bp[n0 + wn * 64];
            #pragma unroll
            for (int nt = 0; nt < 8; nt++) {
                const int c = nt * 8 + t4 * 2;
                float2 rv;
                rv.x = fmaxf(acc[mt][nt][half * 2 + 0] + bptr[c + 0], 0.f);
                rv.y = fmaxf(acc[mt][nt][half * 2 + 1] + bptr[c + 1], 0.f);
                *(float2*)&dst[c] = rv;
            }
        }
    }
}

// ---------------------------------------------------------------------------
// Causal flash attention, tf32 mma.sync + ldmatrix (R10 math, bit-identical).
// NEW: P is written into the retired Ks buffer in two t-halves (PV split into
// ks 0..7 and 8..15), deleting the 67.6KB Ps buffer entirely.
// smem (floats): Qs[128][68] @0 | KsP[128][68] @8704 | Vst[64][132] @17408
// = 25856 floats = 103424 B  =>  2 CTAs/SM (occupancy 2x vs R10).
// ---------------------------------------------------------------------------
#define ASMEM_BYTES 103424

__global__ __launch_bounds__(256, 2) void attn_mma_kernel()
{
    extern __shared__ float smf[];
    float* Qs  = smf;            // [q][d]  pitch 68
    float* KsP = smf + 8704;     // [kv][d] pitch 68 (K in S phase; P-half in PV)
    float* Vst = smf + 17408;    // [d][t]  pitch 132 (transposed V)

    const int qt = gridDim.x - 1 - blockIdx.x;   // heavy tiles first
    const int h  = blockIdx.y;
    const int b  = blockIdx.z;
    const int q0 = qt * 128;

    const float* Q = g_q + ((size_t)(b * HH + h)) * SS * DD;
    const float* K = g_k + ((size_t)(b * HH + h)) * SS * DD;
    const float* V = g_v + ((size_t)(b * HH + h)) * SS * DD;

    const int tid = threadIdx.x;
    const int lane = tid & 31, w = tid >> 5;
    const int g = lane >> 2, t4 = lane & 3;
    const int r0l = w * 16 + g;          // local row (and +8)

    const uint32_t Qs_u32  = smem_to_u32(Qs);
    const uint32_t KsP_u32 = smem_to_u32(KsP);
    const uint32_t Vst_u32 = smem_to_u32(Vst);

    // ldmatrix per-lane addressing
    const int Lq = lane & 7, grp = lane >> 3;
    const int offQ = (w * 16 + (grp & 1) * 8 + Lq) * 68  + (grp >> 1) * 4;  // A frag (Qs / P-half)
    const int offK = ((grp >> 1) * 8 + Lq) * 68          + (grp & 1) * 4;   // B frag (Ks)
    const int offV = ((grp >> 1) * 8 + Lq) * 132         + (grp & 1) * 4;   // B frag (Vst)

    // load Q tile (coalesced, conflict-free)
    #pragma unroll
    for (int ii = 0; ii < 32; ii++) {
        int idx = tid + ii * 256;
        int r = idx >> 6, e = idx & 63;
        Qs[r * 68 + e] = Q[(size_t)(q0 + r) * DD + e];
    }

    float oacc[8][4] = {};
    float m0r = -1e30f, m1r = -1e30f, l0r = 0.f, l1r = 0.f;

    for (int kt = 0; kt <= qt; kt++) {
        __syncthreads();   // prev iter done with KsP/Vst (and Qs stores on iter 0)
        #pragma unroll
        for (int ii = 0; ii < 32; ii++) {
            int idx = tid + ii * 256;
            int c = idx >> 6, e = idx & 63;
            KsP[c * 68 + e]  = K[(size_t)(kt * 128 + c) * DD + e];
            Vst[e * 132 + c] = V[(size_t)(kt * 128 + c) * DD + e];   // transpose
        }
        __syncthreads();

        // ---- S = Q K^T : 16 n-tiles x 8 k-steps of m16n8k8 ----
        float sacc[16][4];
        #pragma unroll
        for (int nt = 0; nt < 16; nt++)
            #pragma unroll
            for (int j = 0; j < 4; j++) sacc[nt][j] = 0.f;

        #pragma unroll
        for (int kd = 0; kd < 8; kd++) {
            uint32_t af[4];
            ldm_x4(af, Qs_u32 + (offQ + kd * 8) * 4);
            #pragma unroll
            for (int ntp = 0; ntp < 8; ntp++) {
                uint32_t tb[4];
                ldm_x4(tb, KsP_u32 + (offK + ntp * 16 * 68 + kd * 8) * 4);
                mma16n8k8(sacc[2 * ntp],     af, &tb[0]);
                mma16n8k8(sacc[2 * ntp + 1], af, &tb[2]);
            }
        }

        // ---- scale + causal mask ----
        const bool diag = (kt == qt);
        #pragma unroll
        for (int nt = 0; nt < 16; nt++) {
            #pragma unroll
            for (int j = 0; j < 4; j++) {
                int c  = nt * 8 + t4 * 2 + (j & 1);
                int rl = r0l + ((j >> 1) * 8);
                float sv = sacc[nt][j] * 0.125f;
                if (diag && c > rl) sv = -1e30f;
                sacc[nt][j] = sv;
            }
        }

        // ---- online softmax (rows g and g+8 of warp slab) ----
        float mx0 = -1e30f, mx1 = -1e30f;
        #pragma unroll
        for (int nt = 0; nt < 16; nt++) {
            mx0 = fmaxf(mx0, fmaxf(sacc[nt][0], sacc[nt][1]));
            mx1 = fmaxf(mx1, fmaxf(sacc[nt][2], sacc[nt][3]));
        }
        mx0 = fmaxf(mx0, __shfl_xor_sync(0xffffffffu, mx0, 1));
        mx0 = fmaxf(mx0, __shfl_xor_sync(0xffffffffu, mx0, 2));
        mx1 = fmaxf(mx1, __shfl_xor_sync(0xffffffffu, mx1, 1));
        mx1 = fmaxf(mx1, __shfl_xor_sync(0xffffffffu, mx1, 2));

        float mn0 = fmaxf(m0r, mx0), mn1 = fmaxf(m1r, mx1);
        float f0 = __expf(m0r - mn0), f1 = __expf(m1r - mn1);
        m0r = mn0; m1r = mn1;

        float s0 = 0.f, s1 = 0.f;
        #pragma unroll
        for (int nt = 0; nt < 16; nt++) {
            float p0 = __expf(sacc[nt][0] - mn0);
            float p1 = __expf(sacc[nt][1] - mn0);
            float p2 = __expf(sacc[nt][2] - mn1);
            float p3 = __expf(sacc[nt][3] - mn1);
            s0 += p0 + p1; s1 += p2 + p3;
            // round to tf32 grid once (PV mma truncates operands)
            sacc[nt][0] = rna_tf32(p0); sacc[nt][1] = rna_tf32(p1);
            sacc[nt][2] = rna_tf32(p2); sacc[nt][3] = rna_tf32(p3);
        }
        s0 += __shfl_xor_sync(0xffffffffu, s0, 1);
        s0 += __shfl_xor_sync(0xffffffffu, s0, 2);
        s1 += __shfl_xor_sync(0xffffffffu, s1, 1);
        s1 += __shfl_xor_sync(0xffffffffu, s1, 2);
        l0r = l0r * f0 + s0;
        l1r = l1r * f1 + s1;

        #pragma unroll
        for (int nt = 0; nt < 8; nt++) {
            oacc[nt][0] *= f0; oacc[nt][1] *= f0;
            oacc[nt][2] *= f1; oacc[nt][3] *= f1;
        }

        // ---- O += P V in two t-halves through the retired Ks buffer ----
        #pragma unroll
        for (int hf = 0; hf < 2; hf++) {
            __syncthreads();   // hf=0: Ks reads done; hf=1: half-0 reads done
            #pragma unroll
            for (int ntl = 0; ntl < 8; ntl++) {
                const int nt = hf * 8 + ntl;
                *(float2*)&KsP[r0l * 68 + ntl * 8 + t4 * 2] =
                    make_float2(sacc[nt][0], sacc[nt][1]);
                *(float2*)&KsP[(r0l + 8) * 68 + ntl * 8 + t4 * 2] =
                    make_float2(sacc[nt][2], sacc[nt][3]);
            }
            __syncthreads();
            #pragma unroll
            for (int ksl = 0; ksl < 8; ksl++) {
                uint32_t af[4];
                ldm_x4(af, KsP_u32 + (offQ + ksl * 8) * 4);
                #pragma unroll
                for (int ntp = 0; ntp < 4; ntp++) {
                    uint32_t tb[4];
                    ldm_x4(tb, Vst_u32 + (offV + ntp * 16 * 132 + (hf * 8 + ksl) * 8) * 4);
                    mma16n8k8(oacc[2 * ntp],     af, &tb[0]);
                    mma16n8k8(oacc[2 * ntp + 1], af, &tb[2]);
                }
            }
        }
    }

    // epilogue: normalize, round, store concat-ready [B,S,H*D]
    const float inv0 = 1.0f / l0r, inv1 = 1.0f / l1r;
    const int gr0 = q0 + r0l, gr1 = gr0 + 8;
    float* dst0 = &g_attn[(((size_t)(b * SS + gr0)) * HH + h) * DD];
    float* dst1 = &g_attn[(((size_t)(b * SS + gr1)) * HH + h) * DD];
    #pragma unroll
    for (int nt = 0; nt < 8; nt++) {
        const int d = nt * 8 + t4 * 2;
        float2 r0v = make_float2(rna_tf32(oacc[nt][0] * inv0), rna_tf32(oacc[nt][1] * inv0));
        float2 r1v = make_float2(rna_tf32(oacc[nt][2] * inv1), rna_tf32(oacc[nt][3] * inv1));
        *(float2*)&dst0[d] = r0v;
        *(float2*)&dst1[d] = r1v;
    }
}

// ============================ host side ============================
extern "C" void kernel_launch(void* const* d_in, const int* in_sizes, int n_in,
                              void* d_out, int out_size)
{
    const float* x  = (const float*)d_in[0];
    const float* Wq = (const float*)d_in[1];
    const float* Wk = (const float*)d_in[2];
    const float* Wv = (const float*)d_in[3];
    const float* bq = (const float*)d_in[4];
    const float* bk = (const float*)d_in[5];
    const float* bv = (const float*)d_in[6];
    const float* Wp = (const float*)d_in[7];
    const float* bp = (const float*)d_in[8];
    float* out = (float*)d_out;
    (void)in_sizes; (void)n_in; (void)out_size;

    cudaFuncSetAttribute(gemm_proj_kernel,
                         cudaFuncAttributeMaxDynamicSharedMemorySize, GSMEM_BYTES);
    cudaFuncSetAttribute(gemm_out_kernel,
                         cudaFuncAttributeMaxDynamicSharedMemorySize, GSMEM_BYTES);
    cudaFuncSetAttribute(attn_mma_kernel,
                         cudaFuncAttributeMaxDynamicSharedMemorySize, ASMEM_BYTES);

    round_x_kernel<<<1024, 256>>>(x);
    transpose_w_kernel<<<dim3(EE / 32, DD / 32, 48), 256>>>(Wq, Wk, Wv);
    transpose_wp_kernel<<<dim3(EE / 32, EE / 32), 256>>>(Wp);

    gemm_proj_kernel<<<dim3(3 * EE / 128, MTOT / 128), 256, GSMEM_BYTES>>>(bq, bk, bv);

    attn_mma_kernel<<<dim3(SS / 128, HH, BB), 256, ASMEM_BYTES>>>();

    gemm_out_kernel<<<dim3(EE / 128, MTOT / 128), 256, GSMEM_BYTES>>>(bp, out);
}

// round 14
// speedup vs baseline: 1.1039x; 1.1039x over previous
#include <cuda_runtime.h>
#include <cstdint>

// Problem shape (fixed)
#define BB 2
#define SS 2048
#define EE 1024
#define HH 16
#define DD 64
#define MTOT (BB*SS)   // 4096

// Scratch (device globals)
__device__ float g_xr[MTOT*EE];        // x rounded to tf32 grid
__device__ float g_wt[3*EE*EE];        // W{q,k,v}^T: [which][n=h*64+d][e], rna-rounded
__device__ float g_wpt[EE*EE];         // Wp^T: [n][k], rna-rounded
__device__ float g_q[BB*HH*SS*DD];     // [B,H,S,D], rna-rounded
__device__ float g_k[BB*HH*SS*DD];
__device__ float g_v[BB*HH*SS*DD];
__device__ float g_attn[BB*SS*HH*DD];  // [B,S,H*D], rna-rounded

// ============================ helpers ============================
__device__ __forceinline__ uint32_t smem_to_u32(const void* p) {
    uint32_t a;
    asm("{ .reg .u64 t; cvta.to.shared.u64 t, %1; cvt.u32.u64 %0, t; }" : "=r"(a) : "l"(p));
    return a;
}
__device__ __forceinline__ float rna_tf32(float v) {
    float r; asm("cvt.rna.tf32.f32 %0, %1;" : "=f"(r) : "f"(v)); return r;
}
__device__ __forceinline__ void ldgsts16(uint32_t s, const float* g) {
    asm volatile("cp.async.cg.shared.global [%0], [%1], 16;" :: "r"(s), "l"(g) : "memory");
}
#define CP_COMMIT() asm volatile("cp.async.commit_group;" ::: "memory")
#define CP_WAIT3()  asm volatile("cp.async.wait_group 3;" ::: "memory")
#define CP_WAIT0()  asm volatile("cp.async.wait_group 0;" ::: "memory")

// m16n8k8 tf32 mma: D += A*B   (fragment conventions validated in R5/R6)
__device__ __forceinline__ void mma16n8k8(float* d, const uint32_t* a, const uint32_t* b) {
    asm volatile(
        "mma.sync.aligned.m16n8k8.row.col.f32.tf32.tf32.f32 "
        "{%0,%1,%2,%3}, {%4,%5,%6,%7}, {%8,%9}, {%0,%1,%2,%3};\n"
        : "+f"(d[0]), "+f"(d[1]), "+f"(d[2]), "+f"(d[3])
        : "r"(a[0]), "r"(a[1]), "r"(a[2]), "r"(a[3]), "r"(b[0]), "r"(b[1]));
}

// ldmatrix x4: four 8-row x 16B matrices; lane groups 0-7/8-15/16-23/24-31
// supply row addresses for matrices 0..3 -> dest regs r[0..3].
__device__ __forceinline__ void ldm_x4(uint32_t* r, uint32_t addr) {
    asm volatile("ldmatrix.sync.aligned.m8n8.x4.shared.b16 {%0,%1,%2,%3}, [%4];"
        : "=r"(r[0]), "=r"(r[1]), "=r"(r[2]), "=r"(r[3]) : "r"(addr));
}

// ============================ prep kernels ============================
__global__ __launch_bounds__(256) void round_x_kernel(const float* __restrict__ x)
{
    int i = blockIdx.x * blockDim.x + threadIdx.x;
    const int n4 = MTOT * EE / 4;
    for (; i < n4; i += gridDim.x * blockDim.x) {
        float4 v = ((const float4*)x)[i];
        v.x = rna_tf32(v.x); v.y = rna_tf32(v.y);
        v.z = rna_tf32(v.z); v.w = rna_tf32(v.w);
        ((float4*)g_xr)[i] = v;
    }
}

__global__ __launch_bounds__(256) void transpose_w_kernel(
    const float* __restrict__ Wq, const float* __restrict__ Wk, const float* __restrict__ Wv)
{
    __shared__ float t[32][33];
    const int zc = blockIdx.z;              // 0..47
    const int which = zc >> 4, h = zc & 15;
    const float* W = ((which == 0) ? Wq : (which == 1) ? Wk : Wv) + (size_t)h * EE * DD;
    const int e0 = blockIdx.x * 32, d0 = blockIdx.y * 32;
    const int tx = threadIdx.x & 31, ty8 = threadIdx.x >> 5;
    #pragma unroll
    for (int i = 0; i < 4; i++) {
        int e = ty8 + i * 8;
        t[e][tx] = rna_tf32(W[(size_t)(e0 + e) * DD + d0 + tx]);
    }
    __syncthreads();
    float* dst = g_wt + (size_t)which * EE * EE;
    #pragma unroll
    for (int i = 0; i < 4; i++) {
        int dr = ty8 + i * 8;
        dst[(size_t)(h * DD + d0 + dr) * EE + e0 + tx] = t[tx][dr];
    }
}

__global__ __launch_bounds__(256) void transpose_wp_kernel(const float* __restrict__ Wp)
{
    __shared__ float t[32][33];
    const int k0 = blockIdx.x * 32, n0 = blockIdx.y * 32;
    const int tx = threadIdx.x & 31, ty8 = threadIdx.x >> 5;
    #pragma unroll
    for (int i = 0; i < 4; i++) {
        int k = ty8 + i * 8;
        t[k][tx] = rna_tf32(Wp[(size_t)(k0 + k) * EE + n0 + tx]);
    }
    __syncthreads();
    #pragma unroll
    for (int i = 0; i < 4; i++) {
        int nr = ty8 + i * 8;
        g_wpt[(size_t)(n0 + nr) * EE + k0 + tx] = t[tx][nr];
    }
}

// ============================ mma.sync GEMM core ============================
// 5-stage cp.async pipeline, one __syncthreads per k-tile; ldmatrix fragments.
// Store at iter t targets stage (t-1) mod 5, protected by the top-of-t barrier.
#define PITCH   20
#define STAGE_F (2*128*PITCH)      // 5120 floats per stage
#define NSTAGE  5
#define GSMEM_BYTES (NSTAGE*STAGE_F*4)  // 102400

__device__ __forceinline__ void gemm_load_stage(
    uint32_t smem_u32, int s, const float* __restrict__ Ag, const float* __restrict__ Bg,
    int m0, int n0, int kt, int tid)
{
    const uint32_t baseA = smem_u32 + s * (STAGE_F * 4);
    const uint32_t baseB = baseA + 128 * PITCH * 4;
    #pragma unroll
    for (int i = 0; i < 2; i++) {
        int cid = tid + i * 256;
        int r = cid >> 2, c = cid & 3;
        ldgsts16(baseA + (r * PITCH + c * 4) * 4, Ag + (size_t)(m0 + r) * EE + kt * 16 + c * 4);
        ldgsts16(baseB + (r * PITCH + c * 4) * 4, Bg + (size_t)(n0 + r) * EE + kt * 16 + c * 4);
    }
    CP_COMMIT();
}

__device__ __forceinline__ void gemm_mainloop_mma(
    const float* __restrict__ Ag, const float* __restrict__ Bg,
    int m0, int n0, float acc[2][8][4], float* __restrict__ sm)
{
    const int tid  = threadIdx.x;
    const int lane = tid & 31, wid = tid >> 5;
    const int wm = wid & 3, wn = wid >> 2;
    const uint32_t smem_u32 = smem_to_u32(sm);

    const int Lq = lane & 7, grp = lane >> 3;
    const int offA = (wm * 32 + (grp & 1) * 8 + Lq) * PITCH + (grp >> 1) * 4;
    const int offB = (wn * 64 + (grp >> 1) * 8 + Lq) * PITCH + (grp & 1) * 4;

    gemm_load_stage(smem_u32, 0, Ag, Bg, m0, n0, 0, tid);
    gemm_load_stage(smem_u32, 1, Ag, Bg, m0, n0, 1, tid);
    gemm_load_stage(smem_u32, 2, Ag, Bg, m0, n0, 2, tid);
    gemm_load_stage(smem_u32, 3, Ag, Bg, m0, n0, 3, tid);

    const int KT = EE / 16;   // 64
    int s = 0, ls = 4;        // compute stage, load stage (t+4) mod 5
    for (int t = 0; t < KT; t++) {
        CP_WAIT3();            // group t complete (<=3 groups pending)
        __syncthreads();       // stage t visible; readers of stage (t-1)%5 done

        if (t + 4 < KT) gemm_load_stage(smem_u32, ls, Ag, Bg, m0, n0, t + 4, tid);
        else            CP_COMMIT();   // keep one-group-per-iter accounting

        const uint32_t aBase = smem_u32 + s * (STAGE_F * 4);
        const uint32_t bBase = aBase + 128 * PITCH * 4;
        #pragma unroll
        for (int ks = 0; ks < 16; ks += 8) {
            uint32_t af[2][4], bf[8][2];
            ldm_x4(af[0], aBase + (offA + ks) * 4);
            ldm_x4(af[1], aBase + (offA + 16 * PITCH + ks) * 4);
            #pragma unroll
            for (int ntp = 0; ntp < 4; ntp++) {
                uint32_t tb[4];
                ldm_x4(tb, bBase + (offB + ntp * 16 * PITCH + ks) * 4);
                bf[2 * ntp][0] = tb[0]; bf[2 * ntp][1] = tb[1];
                bf[2 * ntp + 1][0] = tb[2]; bf[2 * ntp + 1][1] = tb[3];
            }
            #pragma unroll
            for (int mt = 0; mt < 2; mt++)
                #pragma unroll
                for (int nt = 0; nt < 8; nt++)
                    mma16n8k8(acc[mt][nt], af[mt], bf[nt]);
        }
        s  = (s  == NSTAGE - 1) ? 0 : s + 1;
        ls = (ls == NSTAGE - 1) ? 0 : ls + 1;
    }
}

// ---------------------------------------------------------------------------
// QKV projection: scatter + bias into g_q/g_k/g_v (rna-rounded for attn mma).
// ---------------------------------------------------------------------------
__global__ __launch_bounds__(256) void gemm_proj_kernel(
    const float* __restrict__ bq, const float* __restrict__ bk, const float* __restrict__ bv)
{
    extern __shared__ __align__(16) float sm[];
    const int n0 = blockIdx.x * 128;
    const int m0 = blockIdx.y * 128;

    float acc[2][8][4] = {};
    gemm_mainloop_mma(g_xr, g_wt, m0, n0, acc, sm);

    const int which = n0 >> 10;
    const int h0 = (n0 & 1023) >> 6;
    const float* bias = (which == 0) ? bq : (which == 1) ? bk : bv;
    float*       outp = (which == 0) ? g_q : (which == 1) ? g_k : g_v;

    const int lane = threadIdx.x & 31, wid = threadIdx.x >> 5;
    const int g = lane >> 2, t4 = lane & 3;
    const int wm = wid & 3, wn = wid >> 2;
    const int hh = h0 + wn;

    #pragma unroll
    for (int mt = 0; mt < 2; mt++) {
        #pragma unroll
        for (int half = 0; half < 2; half++) {
            const int row = m0 + wm * 32 + mt * 16 + g + half * 8;
            const int bi = row >> 11, sidx = row & (SS - 1);
            float* dst = &outp[(((size_t)(bi * HH + hh)) * SS + sidx) * DD];
            #pragma unroll
            for (int nt = 0; nt < 8; nt++) {
                const int d = nt * 8 + t4 * 2;
                float2 rv;
                rv.x = rna_tf32(acc[mt][nt][half * 2 + 0] + bias[hh * DD + d + 0]);
                rv.y = rna_tf32(acc[mt][nt][half * 2 + 1] + bias[hh * DD + d + 1]);
                *(float2*)&dst[d] = rv;
            }
        }
    }
}

// ---------------------------------------------------------------------------
// Output projection: out = relu(g_attn @ g_wpt^T + bp)
// ---------------------------------------------------------------------------
__global__ __launch_bounds__(256) void gemm_out_kernel(
    const float* __restrict__ bp, float* __restrict__ out)
{
    extern __shared__ __align__(16) float sm[];
    const int n0 = blockIdx.x * 128;
    const int m0 = blockIdx.y * 128;

    float acc[2][8][4] = {};
    gemm_mainloop_mma(g_attn, g_wpt, m0, n0, acc, sm);

    const int lane = threadIdx.x & 31, wid = threadIdx.x >> 5;
    const int g = lane >> 2, t4 = lane & 3;
    const int wm = wid & 3, wn = wid >> 2;

    #pragma unroll
    for (int mt = 0; mt < 2; mt++) {
        #pragma unroll
        for (int half = 0; half < 2; half++) {
            const int row = m0 + wm * 32 + mt * 16 + g + half * 8;
            float* dst = &out[(size_t)row * EE + n0 + wn * 64];
            const float* bptr = &bp[n0 + wn * 64];
            #pragma unroll
            for (int nt = 0; nt < 8; nt++) {
                const int c = nt * 8 + t4 * 2;
                float2 rv;
                rv.x = fmaxf(acc[mt][nt][half * 2 + 0] + bptr[c + 0], 0.f);
                rv.y = fmaxf(acc[mt][nt][half * 2 + 1] + bptr[c + 1], 0.f);
                *(float2*)&dst[c] = rv;
            }
        }
    }
}

// ---------------------------------------------------------------------------
// Causal flash attention, tf32 mma.sync + ldmatrix (R10 structure — best).
// K tile and Q tile arrive via cp.async (issued before the scalar V transpose,
// completing in its shadow); V path unchanged.
// smem (floats): Qs[128][68] @0 | Ks[128][68] @8704 | Vst[64][132] @17408 |
//                Ps[128][132] @25856 ; total 42752 floats = 171008 B.
// ---------------------------------------------------------------------------
#define ASMEM_BYTES 171008

__global__ __launch_bounds__(256, 1) void attn_mma_kernel()
{
    extern __shared__ float smf[];
    float* Qs  = smf;            // [q][d]  pitch 68
    float* Ks  = smf + 8704;     // [kv][d] pitch 68
    float* Vst = smf + 17408;    // [d][t]  pitch 132 (transposed V)
    float* Ps  = smf + 25856;    // [q][t]  pitch 132

    const int qt = gridDim.x - 1 - blockIdx.x;   // heavy tiles first
    const int h  = blockIdx.y;
    const int b  = blockIdx.z;
    const int q0 = qt * 128;

    const float* Q = g_q + ((size_t)(b * HH + h)) * SS * DD;
    const float* K = g_k + ((size_t)(b * HH + h)) * SS * DD;
    const float* V = g_v + ((size_t)(b * HH + h)) * SS * DD;

    const int tid = threadIdx.x;
    const int lane = tid & 31, w = tid >> 5;
    const int g = lane >> 2, t4 = lane & 3;
    const int r0l = w * 16 + g;          // local row (and +8)

    const uint32_t Qs_u32  = smem_to_u32(Qs);
    const uint32_t Ks_u32  = smem_to_u32(Ks);
    const uint32_t Vst_u32 = smem_to_u32(Vst);
    const uint32_t Ps_u32  = smem_to_u32(Ps);

    // ldmatrix per-lane addressing
    const int Lq = lane & 7, grp = lane >> 3;
    const int offQ = (w * 16 + (grp & 1) * 8 + Lq) * 68  + (grp >> 1) * 4;  // A frag
    const int offK = ((grp >> 1) * 8 + Lq) * 68          + (grp & 1) * 4;   // B frag
    const int offP = (w * 16 + (grp & 1) * 8 + Lq) * 132 + (grp >> 1) * 4;  // A frag
    const int offV = ((grp >> 1) * 8 + Lq) * 132         + (grp & 1) * 4;   // B frag

    // cp.async copy coords (16B granules): 2048 granules, 8 per thread
    const int c16 = tid >> 4;            // base row (step 16)
    const int e4  = (tid & 15) * 4;      // float offset within row

    // load Q tile via cp.async (completes under the first kv-tile wait)
    #pragma unroll
    for (int ii = 0; ii < 8; ii++) {
        int r = c16 + ii * 16;
        ldgsts16(Qs_u32 + (r * 68 + e4) * 4, Q + (size_t)(q0 + r) * DD + e4);
    }
    CP_COMMIT();

    float oacc[8][4] = {};
    float m0r = -1e30f, m1r = -1e30f, l0r = 0.f, l1r = 0.f;

    for (int kt = 0; kt <= qt; kt++) {
        __syncthreads();   // prev iter done with Ks/Vst/Ps
        // K tile: cp.async, overlapped with the scalar V transpose below
        #pragma unroll
        for (int ii = 0; ii < 8; ii++) {
            int c = c16 + ii * 16;
            ldgsts16(Ks_u32 + (c * 68 + e4) * 4, K + (size_t)(kt * 128 + c) * DD + e4);
        }
        CP_COMMIT();
        // V tile: scalar transpose (unchanged from R10)
        #pragma unroll
        for (int ii = 0; ii < 32; ii++) {
            int idx = tid + ii * 256;
            int c = idx >> 6, e = idx & 63;
            Vst[e * 132 + c] = V[(size_t)(kt * 128 + c) * DD + e];
        }
        CP_WAIT0();        // K (and, on iter 0, Q) in smem
        __syncthreads();

        // ---- S = Q K^T : 16 n-tiles x 8 k-steps of m16n8k8 ----
        float sacc[16][4];
        #pragma unroll
        for (int nt = 0; nt < 16; nt++)
            #pragma unroll
            for (int j = 0; j < 4; j++) sacc[nt][j] = 0.f;

        #pragma unroll
        for (int kd = 0; kd < 8; kd++) {
            uint32_t af[4];
            ldm_x4(af, Qs_u32 + (offQ + kd * 8) * 4);
            #pragma unroll
            for (int ntp = 0; ntp < 8; ntp++) {
                uint32_t tb[4];
                ldm_x4(tb, Ks_u32 + (offK + ntp * 16 * 68 + kd * 8) * 4);
                mma16n8k8(sacc[2 * ntp],     af, &tb[0]);
                mma16n8k8(sacc[2 * ntp + 1], af, &tb[2]);
            }
        }

        // ---- scale + causal mask ----
        const bool diag = (kt == qt);
        #pragma unroll
        for (int nt = 0; nt < 16; nt++) {
            #pragma unroll
            for (int j = 0; j < 4; j++) {
                int c  = nt * 8 + t4 * 2 + (j & 1);
                int rl = r0l + ((j >> 1) * 8);
                float sv = sacc[nt][j] * 0.125f;
                if (diag && c > rl) sv = -1e30f;
                sacc[nt][j] = sv;
            }
        }

        // ---- online softmax (rows g and g+8 of warp slab) ----
        float mx0 = -1e30f, mx1 = -1e30f;
        #pragma unroll
        for (int nt = 0; nt < 16; nt++) {
            mx0 = fmaxf(mx0, fmaxf(sacc[nt][0], sacc[nt][1]));
            mx1 = fmaxf(mx1, fmaxf(sacc[nt][2], sacc[nt][3]));
        }
        mx0 = fmaxf(mx0, __shfl_xor_sync(0xffffffffu, mx0, 1));
        mx0 = fmaxf(mx0, __shfl_xor_sync(0xffffffffu, mx0, 2));
        mx1 = fmaxf(mx1, __shfl_xor_sync(0xffffffffu, mx1, 1));
        mx1 = fmaxf(mx1, __shfl_xor_sync(0xffffffffu, mx1, 2));

        float mn0 = fmaxf(m0r, mx0), mn1 = fmaxf(m1r, mx1);
        float f0 = __expf(m0r - mn0), f1 = __expf(m1r - mn1);
        m0r = mn0; m1r = mn1;

        float s0 = 0.f, s1 = 0.f;
        #pragma unroll
        for (int nt = 0; nt < 16; nt++) {
            float p0 = __expf(sacc[nt][0] - mn0);
            float p1 = __expf(sacc[nt][1] - mn0);
            float p2 = __expf(sacc[nt][2] - mn1);
            float p3 = __expf(sacc[nt][3] - mn1);
            sacc[nt][0] = p0; sacc[nt][1] = p1; sacc[nt][2] = p2; sacc[nt][3] = p3;
            s0 += p0 + p1; s1 += p2 + p3;
        }
        s0 += __shfl_xor_sync(0xffffffffu, s0, 1);
        s0 += __shfl_xor_sync(0xffffffffu, s0, 2);
        s1 += __shfl_xor_sync(0xffffffffu, s1, 1);
        s1 += __shfl_xor_sync(0xffffffffu, s1, 2);
        l0r = l0r * f0 + s0;
        l1r = l1r * f1 + s1;

        #pragma unroll
        for (int nt = 0; nt < 8; nt++) {
            oacc[nt][0] *= f0; oacc[nt][1] *= f0;
            oacc[nt][2] *= f1; oacc[nt][3] *= f1;
        }

        // ---- write P to smem (rna-rounded: mma truncates operands) ----
        #pragma unroll
        for (int nt = 0; nt < 16; nt++) {
            float2 p01 = make_float2(rna_tf32(sacc[nt][0]), rna_tf32(sacc[nt][1]));
            float2 p23 = make_float2(rna_tf32(sacc[nt][2]), rna_tf32(sacc[nt][3]));
            *(float2*)&Ps[r0l * 132 + nt * 8 + t4 * 2]       = p01;
            *(float2*)&Ps[(r0l + 8) * 132 + nt * 8 + t4 * 2] = p23;
        }
        __syncthreads();

        // ---- O += P V : 16 k-steps x 8 n-tiles (ldmatrix fragments) ----
        #pragma unroll
        for (int ks = 0; ks < 16; ks++) {
            uint32_t af[4];
            ldm_x4(af, Ps_u32 + (offP + ks * 8) * 4);
            #pragma unroll
            for (int ntp = 0; ntp < 4; ntp++) {
                uint32_t tb[4];
                ldm_x4(tb, Vst_u32 + (offV + ntp * 16 * 132 + ks * 8) * 4);
                mma16n8k8(oacc[2 * ntp],     af, &tb[0]);
                mma16n8k8(oacc[2 * ntp + 1], af, &tb[2]);
            }
        }
    }

    // epilogue: normalize, round, store concat-ready [B,S,H*D]
    const float inv0 = 1.0f / l0r, inv1 = 1.0f / l1r;
    const int gr0 = q0 + r0l, gr1 = gr0 + 8;
    float* dst0 = &g_attn[(((size_t)(b * SS + gr0)) * HH + h) * DD];
    float* dst1 = &g_attn[(((size_t)(b * SS + gr1)) * HH + h) * DD];
    #pragma unroll
    for (int nt = 0; nt < 8; nt++) {
        const int d = nt * 8 + t4 * 2;
        float2 r0v = make_float2(rna_tf32(oacc[nt][0] * inv0), rna_tf32(oacc[nt][1] * inv0));
        float2 r1v = make_float2(rna_tf32(oacc[nt][2] * inv1), rna_tf32(oacc[nt][3] * inv1));
        *(float2*)&dst0[d] = r0v;
        *(float2*)&dst1[d] = r1v;
    }
}

// ============================ host side ============================
extern "C" void kernel_launch(void* const* d_in, const int* in_sizes, int n_in,
                              void* d_out, int out_size)
{
    const float* x  = (const float*)d_in[0];
    const float* Wq = (const float*)d_in[1];
    const float* Wk = (const float*)d_in[2];
    const float* Wv = (const float*)d_in[3];
    const float* bq = (const float*)d_in[4];
    const float* bk = (const float*)d_in[5];
    const float* bv = (const float*)d_in[6];
    const float* Wp = (const float*)d_in[7];
    const float* bp = (const float*)d_in[8];
    float* out = (float*)d_out;
    (void)in_sizes; (void)n_in; (void)out_size;

    cudaFuncSetAttribute(gemm_proj_kernel,
                         cudaFuncAttributeMaxDynamicSharedMemorySize, GSMEM_BYTES);
    cudaFuncSetAttribute(gemm_out_kernel,
                         cudaFuncAttributeMaxDynamicSharedMemorySize, GSMEM_BYTES);
    cudaFuncSetAttribute(attn_mma_kernel,
                         cudaFuncAttributeMaxDynamicSharedMemorySize, ASMEM_BYTES);

    round_x_kernel<<<1024, 256>>>(x);
    transpose_w_kernel<<<dim3(EE / 32, DD / 32, 48), 256>>>(Wq, Wk, Wv);
    transpose_wp_kernel<<<dim3(EE / 32, EE / 32), 256>>>(Wp);

    gemm_proj_kernel<<<dim3(3 * EE / 128, MTOT / 128), 256, GSMEM_BYTES>>>(bq, bk, bv);

    attn_mma_kernel<<<dim3(SS / 128, HH, BB), 256, ASMEM_BYTES>>>();

    gemm_out_kernel<<<dim3(EE / 128, MTOT / 128), 256, GSMEM_BYTES>>>(bp, out);
}

// round 17
// speedup vs baseline: 1.6602x; 1.5040x over previous
#include <cuda_runtime.h>
#include <cuda_fp16.h>
#include <cstdint>

// Problem shape (fixed)
#define BB 2
#define SS 2048
#define EE 1024
#define HH 16
#define DD 64
#define MTOT (BB*SS)   // 4096

// Scratch (device globals) — all mma operands in fp16 (same mantissa as tf32)
__device__ __half g_xh[MTOT*EE];       // x, rne-rounded to fp16
__device__ __half g_wt[3*EE*EE];       // W{q,k,v}^T: [n=which*1024+h*64+d][e]
__device__ __half g_wpt[EE*EE];        // Wp^T: [n][k]
__device__ __half g_q[BB*HH*SS*DD];    // [B,H,S,D]
__device__ __half g_k[BB*HH*SS*DD];
__device__ __half g_v[BB*HH*SS*DD];
__device__ __half g_attn[BB*SS*HH*DD]; // [B,S,H*D]

// ============================ helpers ============================
__device__ __forceinline__ uint32_t smem_to_u32(const void* p) {
    uint32_t a;
    asm("{ .reg .u64 t; cvta.to.shared.u64 t, %1; cvt.u32.u64 %0, t; }" : "=r"(a) : "l"(p));
    return a;
}
__device__ __forceinline__ void ldgsts16(uint32_t s, const void* g) {
    asm volatile("cp.async.cg.shared.global [%0], [%1], 16;" :: "r"(s), "l"(g) : "memory");
}
#define CP_COMMIT() asm volatile("cp.async.commit_group;" ::: "memory")
#define CP_WAIT2()  asm volatile("cp.async.wait_group 2;" ::: "memory")
#define CP_WAIT0()  asm volatile("cp.async.wait_group 0;" ::: "memory")

// m16n8k16 fp16 mma, fp32 accumulate
__device__ __forceinline__ void mma16n8k16(float* d, const uint32_t* a, const uint32_t* b) {
    asm volatile(
        "mma.sync.aligned.m16n8k16.row.col.f32.f16.f16.f32 "
        "{%0,%1,%2,%3}, {%4,%5,%6,%7}, {%8,%9}, {%0,%1,%2,%3};\n"
        : "+f"(d[0]), "+f"(d[1]), "+f"(d[2]), "+f"(d[3])
        : "r"(a[0]), "r"(a[1]), "r"(a[2]), "r"(a[3]), "r"(b[0]), "r"(b[1]));
}

// ldmatrix x4 (b16 native): lane groups 0-7/8-15/16-23/24-31 address mats 0..3
__device__ __forceinline__ void ldm_x4(uint32_t* r, uint32_t addr) {
    asm volatile("ldmatrix.sync.aligned.m8n8.x4.shared.b16 {%0,%1,%2,%3}, [%4];"
        : "=r"(r[0]), "=r"(r[1]), "=r"(r[2]), "=r"(r[3]) : "r"(addr));
}

// ============================ prep kernels ============================
__global__ __launch_bounds__(256) void conv_x_kernel(const float* __restrict__ x)
{
    int i = blockIdx.x * blockDim.x + threadIdx.x;
    const int n4 = MTOT * EE / 4;
    for (; i < n4; i += gridDim.x * blockDim.x) {
        float4 v = ((const float4*)x)[i];
        ((__half2*)g_xh)[2 * i + 0] = __floats2half2_rn(v.x, v.y);
        ((__half2*)g_xh)[2 * i + 1] = __floats2half2_rn(v.z, v.w);
    }
}

__global__ __launch_bounds__(256) void transpose_w_kernel(
    const float* __restrict__ Wq, const float* __restrict__ Wk, const float* __restrict__ Wv)
{
    __shared__ float t[32][33];
    const int zc = blockIdx.z;              // 0..47
    const int which = zc >> 4, h = zc & 15;
    const float* W = ((which == 0) ? Wq : (which == 1) ? Wk : Wv) + (size_t)h * EE * DD;
    const int e0 = blockIdx.x * 32, d0 = blockIdx.y * 32;
    const int tx = threadIdx.x & 31, ty8 = threadIdx.x >> 5;
    #pragma unroll
    for (int i = 0; i < 4; i++) {
        int e = ty8 + i * 8;
        t[e][tx] = W[(size_t)(e0 + e) * DD + d0 + tx];
    }
    __syncthreads();
    __half* dst = g_wt + (size_t)which * EE * EE;
    #pragma unroll
    for (int i = 0; i < 4; i++) {
        int dr = ty8 + i * 8;
        dst[(size_t)(h * DD + d0 + dr) * EE + e0 + tx] = __float2half_rn(t[tx][dr]);
    }
}

__global__ __launch_bounds__(256) void transpose_wp_kernel(const float* __restrict__ Wp)
{
    __shared__ float t[32][33];
    const int k0 = blockIdx.x * 32, n0 = blockIdx.y * 32;
    const int tx = threadIdx.x & 31, ty8 = threadIdx.x >> 5;
    #pragma unroll
    for (int i = 0; i < 4; i++) {
        int k = ty8 + i * 8;
        t[k][tx] = Wp[(size_t)(k0 + k) * EE + n0 + tx];
    }
    __syncthreads();
    #pragma unroll
    for (int i = 0; i < 4; i++) {
        int nr = ty8 + i * 8;
        g_wpt[(size_t)(n0 + nr) * EE + k0 + tx] = __float2half_rn(t[tx][nr]);
    }
}

// ============================ mma.sync fp16 GEMM core ============================
// 4-stage cp.async pipeline, one __syncthreads per k-tile (K=32 halves/stage).
// Pitch 40 halves (80B): ldmatrix rows hit distinct bank groups (20r mod 32).
#define PITCHH  40
#define STAGE_H (2*128*PITCHH)        // 10240 halves per stage
#define NSTAGE  4
#define GSMEM_BYTES (NSTAGE*STAGE_H*2)  // 81920

__device__ __forceinline__ void gemm_load_stage(
    uint32_t smem_u32, int s, const __half* __restrict__ Ag, const __half* __restrict__ Bg,
    int m0, int n0, int kt, int tid)
{
    const uint32_t baseA = smem_u32 + s * (STAGE_H * 2);
    const uint32_t baseB = baseA + 128 * PITCHH * 2;
    #pragma unroll
    for (int i = 0; i < 2; i++) {
        int ga = tid + i * 256;           // 512 granules per tile
        int r = ga >> 2, c8 = ga & 3;     // row, 8-half chunk
        ldgsts16(baseA + (r * PITCHH + c8 * 8) * 2,
                 Ag + (size_t)(m0 + r) * EE + kt * 32 + c8 * 8);
        ldgsts16(baseB + (r * PITCHH + c8 * 8) * 2,
                 Bg + (size_t)(n0 + r) * EE + kt * 32 + c8 * 8);
    }
    CP_COMMIT();
}

__device__ __forceinline__ void gemm_mainloop_mma(
    const __half* __restrict__ Ag, const __half* __restrict__ Bg,
    int m0, int n0, float acc[2][8][4], void* __restrict__ sm)
{
    const int tid  = threadIdx.x;
    const int lane = tid & 31, wid = tid >> 5;
    const int wm = wid & 3, wn = wid >> 2;
    const uint32_t smem_u32 = smem_to_u32(sm);

    const int Lq = lane & 7, grp = lane >> 3;
    // A frag: mats = {m+0,k0},{m+8,k0},{m+0,k8},{m+8,k8}
    const int offA = (wm * 32 + (grp & 1) * 8 + Lq) * PITCHH + (grp >> 1) * 8;
    // B frag pair: mats = {n+0,k0},{n+0,k8},{n+8,k0},{n+8,k8}
    const int offB = (wn * 64 + (grp >> 1) * 8 + Lq) * PITCHH + (grp & 1) * 8;

    gemm_load_stage(smem_u32, 0, Ag, Bg, m0, n0, 0, tid);
    gemm_load_stage(smem_u32, 1, Ag, Bg, m0, n0, 1, tid);
    gemm_load_stage(smem_u32, 2, Ag, Bg, m0, n0, 2, tid);

    const int KT = EE / 32;   // 32
    for (int t = 0; t < KT; t++) {
        const int s = t & 3;
        CP_WAIT2();
        __syncthreads();

        if (t + 3 < KT) gemm_load_stage(smem_u32, (t + 3) & 3, Ag, Bg, m0, n0, t + 3, tid);
        else            CP_COMMIT();

        const uint32_t aBase = smem_u32 + s * (STAGE_H * 2);
        const uint32_t bBase = aBase + 128 * PITCHH * 2;
        #pragma unroll
        for (int ks = 0; ks < 32; ks += 16) {
            uint32_t af[2][4], bf[8][2];
            ldm_x4(af[0], aBase + (offA + ks) * 2);
            ldm_x4(af[1], aBase + (offA + 16 * PITCHH + ks) * 2);
            #pragma unroll
            for (int ntp = 0; ntp < 4; ntp++) {
                uint32_t tb[4];
                ldm_x4(tb, bBase + (offB + ntp * 16 * PITCHH + ks) * 2);
                bf[2 * ntp][0] = tb[0]; bf[2 * ntp][1] = tb[1];
                bf[2 * ntp + 1][0] = tb[2]; bf[2 * ntp + 1][1] = tb[3];
            }
            #pragma unroll
            for (int mt = 0; mt < 2; mt++)
                #pragma unroll
                for (int nt = 0; nt < 8; nt++)
                    mma16n8k16(acc[mt][nt], af[mt], bf[nt]);
        }
    }
}

// ---------------------------------------------------------------------------
// QKV projection: scatter + bias into g_q/g_k/g_v (fp16, rne).
// ---------------------------------------------------------------------------
__global__ __launch_bounds__(256) void gemm_proj_kernel(
    const float* __restrict__ bq, const float* __restrict__ bk, const float* __restrict__ bv)
{
    extern __shared__ __align__(16) char sm[];
    const int n0 = blockIdx.x * 128;
    const int m0 = blockIdx.y * 128;

    float acc[2][8][4] = {};
    gemm_mainloop_mma(g_xh, g_wt, m0, n0, acc, sm);

    const int which = n0 >> 10;
    const int h0 = (n0 & 1023) >> 6;
    const float* bias = (which == 0) ? bq : (which == 1) ? bk : bv;
    __half*      outp = (which == 0) ? g_q : (which == 1) ? g_k : g_v;

    const int lane = threadIdx.x & 31, wid = threadIdx.x >> 5;
    const int g = lane >> 2, t4 = lane & 3;
    const int wm = wid & 3, wn = wid >> 2;
    const int hh = h0 + wn;

    #pragma unroll
    for (int mt = 0; mt < 2; mt++) {
        #pragma unroll
        for (int half = 0; half < 2; half++) {
            const int row = m0 + wm * 32 + mt * 16 + g + half * 8;
            const int bi = row >> 11, sidx = row & (SS - 1);
            __half* dst = &outp[(((size_t)(bi * HH + hh)) * SS + sidx) * DD];
            #pragma unroll
            for (int nt = 0; nt < 8; nt++) {
                const int d = nt * 8 + t4 * 2;
                *(__half2*)&dst[d] = __floats2half2_rn(
                    acc[mt][nt][half * 2 + 0] + bias[hh * DD + d + 0],
                    acc[mt][nt][half * 2 + 1] + bias[hh * DD + d + 1]);
            }
        }
    }
}

// ---------------------------------------------------------------------------
// Output projection: out = relu(g_attn @ g_wpt^T + bp), fp32 output.
// ---------------------------------------------------------------------------
__global__ __launch_bounds__(256) void gemm_out_kernel(
    const float* __restrict__ bp, float* __restrict__ out)
{
    extern __shared__ __align__(16) char sm[];
    const int n0 = blockIdx.x * 128;
    const int m0 = blockIdx.y * 128;

    float acc[2][8][4] = {};
    gemm_mainloop_mma(g_attn, g_wpt, m0, n0, acc, sm);

    const int lane = threadIdx.x & 31, wid = threadIdx.x >> 5;
    const int g = lane >> 2, t4 = lane & 3;
    const int wm = wid & 3, wn = wid >> 2;

    #pragma unroll
    for (int mt = 0; mt < 2; mt++) {
        #pragma unroll
        for (int half = 0; half < 2; half++) {
            const int row = m0 + wm * 32 + mt * 16 + g + half * 8;
            float* dst = &out[(size_t)row * EE + n0 + wn * 64];
            const float* bptr = &bp[n0 + wn * 64];
            #pragma unroll
            for (int nt = 0; nt < 8; nt++) {
                const int c = nt * 8 + t4 * 2;
                float2 rv;
                rv.x = fmaxf(acc[mt][nt][half * 2 + 0] + bptr[c + 0], 0.f);
                rv.y = fmaxf(acc[mt][nt][half * 2 + 1] + bptr[c + 1], 0.f);
                *(float2*)&dst[c] = rv;
            }
        }
    }
}

// ---------------------------------------------------------------------------
// Causal flash attention, fp16 mma.sync + ldmatrix (R10/R13 structure).
// Q/K via cp.async (overlapped with scalar V transpose). fp32 softmax/accum.
// smem (halves): Qs[128][72]@0 | Ks[128][72]@9216 | Vst[64][136]@18432 |
//                Ps[128][136]@27136 ; total 44544 halves = 89088 B -> 2 CTAs/SM.
// ---------------------------------------------------------------------------
#define QK_P 72
#define V_P  136
#define ASMEM_BYTES 89088

__global__ __launch_bounds__(256, 2) void attn_mma_kernel()
{
    extern __shared__ __align__(16) __half smh[];
    __half* Qs  = smh;            // [q][d]  pitch 72
    __half* Ks  = smh + 9216;     // [kv][d] pitch 72
    __half* Vst = smh + 18432;    // [d][t]  pitch 136 (transposed V)
    __half* Ps  = smh + 27136;    // [q][t]  pitch 136

    const int qt = gridDim.x - 1 - blockIdx.x;   // heavy tiles first
    const int h  = blockIdx.y;
    const int b  = blockIdx.z;
    const int q0 = qt * 128;

    const __half* Q = g_q + ((size_t)(b * HH + h)) * SS * DD;
    const __half* K = g_k + ((size_t)(b * HH + h)) * SS * DD;
    const __half* V = g_v + ((size_t)(b * HH + h)) * SS * DD;

    const int tid = threadIdx.x;
    const int lane = tid & 31, w = tid >> 5;
    const int g = lane >> 2, t4 = lane & 3;
    const int r0l = w * 16 + g;          // local row (and +8)

    const uint32_t Qs_u32  = smem_to_u32(Qs);
    const uint32_t Ks_u32  = smem_to_u32(Ks);
    const uint32_t Vst_u32 = smem_to_u32(Vst);
    const uint32_t Ps_u32  = smem_to_u32(Ps);

    // ldmatrix per-lane addressing (half units)
    const int Lq = lane & 7, grp = lane >> 3;
    const int offQ = (w * 16 + (grp & 1) * 8 + Lq) * QK_P + (grp >> 1) * 8;  // A frag
    const int offK = ((grp >> 1) * 8 + Lq) * QK_P         + (grp & 1) * 8;   // B frag
    const int offP = (w * 16 + (grp & 1) * 8 + Lq) * V_P  + (grp >> 1) * 8;  // A frag
    const int offV = ((grp >> 1) * 8 + Lq) * V_P          + (grp & 1) * 8;   // B frag

    // cp.async coords: 128 rows x 8 granules(16B=8 halves) = 1024, 4/thread
    const int c32 = tid >> 3;            // base row (step 32)
    const int e8  = (tid & 7) * 8;       // half offset within row

    // Q tile via cp.async (completes under first kv-tile wait)
    #pragma unroll
    for (int ii = 0; ii < 4; ii++) {
        int r = c32 + ii * 32;
        ldgsts16(Qs_u32 + (r * QK_P + e8) * 2, Q + (size_t)(q0 + r) * DD + e8);
    }
    CP_COMMIT();

    float oacc[8][4] = {};
    float m0r = -1e30f, m1r = -1e30f, l0r = 0.f, l1r = 0.f;

    for (int kt = 0; kt <= qt; kt++) {
        __syncthreads();   // prev iter done with Ks/Vst/Ps
        // K tile: cp.async, overlapped with the scalar V transpose
        #pragma unroll
        for (int ii = 0; ii < 4; ii++) {
            int c = c32 + ii * 32;
            ldgsts16(Ks_u32 + (c * QK_P + e8) * 2, K + (size_t)(kt * 128 + c) * DD + e8);
        }
        CP_COMMIT();
        // V tile: scalar transpose
        #pragma unroll
        for (int ii = 0; ii < 32; ii++) {
            int idx = tid + ii * 256;
            int c = idx >> 6, e = idx & 63;
            Vst[e * V_P + c] = V[(size_t)(kt * 128 + c) * DD + e];
        }
        CP_WAIT0();
        __syncthreads();

        // ---- S = Q K^T : 16 n-tiles x 4 k16-steps ----
        float sacc[16][4];
        #pragma unroll
        for (int nt = 0; nt < 16; nt++)
            #pragma unroll
            for (int j = 0; j < 4; j++) sacc[nt][j] = 0.f;

        #pragma unroll
        for (int kd = 0; kd < 4; kd++) {
            uint32_t af[4];
            ldm_x4(af, Qs_u32 + (offQ + kd * 16) * 2);
            #pragma unroll
            for (int ntp = 0; ntp < 8; ntp++) {
                uint32_t tb[4];
                ldm_x4(tb, Ks_u32 + (offK + ntp * 16 * QK_P + kd * 16) * 2);
                mma16n8k16(sacc[2 * ntp],     af, &tb[0]);
                mma16n8k16(sacc[2 * ntp + 1], af, &tb[2]);
            }
        }

        // ---- scale + causal mask ----
        const bool diag = (kt == qt);
        #pragma unroll
        for (int nt = 0; nt < 16; nt++) {
            #pragma unroll
            for (int j = 0; j < 4; j++) {
                int c  = nt * 8 + t4 * 2 + (j & 1);
                int rl = r0l + ((j >> 1) * 8);
                float sv = sacc[nt][j] * 0.125f;
                if (diag && c > rl) sv = -1e30f;
                sacc[nt][j] = sv;
            }
        }

        // ---- online softmax (rows g and g+8 of warp slab) ----
        float mx0 = -1e30f, mx1 = -1e30f;
        #pragma unroll
        for (int nt = 0; nt < 16; nt++) {
            mx0 = fmaxf(mx0, fmaxf(sacc[nt][0], sacc[nt][1]));
            mx1 = fmaxf(mx1, fmaxf(sacc[nt][2], sacc[nt][3]));
        }
        mx0 = fmaxf(mx0, __shfl_xor_sync(0xffffffffu, mx0, 1));
        mx0 = fmaxf(mx0, __shfl_xor_sync(0xffffffffu, mx0, 2));
        mx1 = fmaxf(mx1, __shfl_xor_sync(0xffffffffu, mx1, 1));
        mx1 = fmaxf(mx1, __shfl_xor_sync(0xffffffffu, mx1, 2));

        float mn0 = fmaxf(m0r, mx0), mn1 = fmaxf(m1r, mx1);
        float f0 = __expf(m0r - mn0), f1 = __expf(m1r - mn1);
        m0r = mn0; m1r = mn1;

        float s0 = 0.f, s1 = 0.f;
        #pragma unroll
        for (int nt = 0; nt < 16; nt++) {
            float p0 = __expf(sacc[nt][0] - mn0);
            float p1 = __expf(sacc[nt][1] - mn0);
            float p2 = __expf(sacc[nt][2] - mn1);
            float p3 = __expf(sacc[nt][3] - mn1);
            sacc[nt][0] = p0; sacc[nt][1] = p1; sacc[nt][2] = p2; sacc[nt][3] = p3;
            s0 += p0 + p1; s1 += p2 + p3;
        }
        s0 += __shfl_xor_sync(0xffffffffu, s0, 1);
        s0 += __shfl_xor_sync(0xffffffffu, s0, 2);
        s1 += __shfl_xor_sync(0xffffffffu, s1, 1);
        s1 += __shfl_xor_sync(0xffffffffu, s1, 2);
        l0r = l0r * f0 + s0;
        l1r = l1r * f1 + s1;

        #pragma unroll
        for (int nt = 0; nt < 8; nt++) {
            oacc[nt][0] *= f0; oacc[nt][1] *= f0;
            oacc[nt][2] *= f1; oacc[nt][3] *= f1;
        }

        // ---- write P to smem as fp16 (rne conversion = operand rounding) ----
        #pragma unroll
        for (int nt = 0; nt < 16; nt++) {
            *(__half2*)&Ps[r0l * V_P + nt * 8 + t4 * 2] =
                __floats2half2_rn(sacc[nt][0], sacc[nt][1]);
            *(__half2*)&Ps[(r0l + 8) * V_P + nt * 8 + t4 * 2] =
                __floats2half2_rn(sacc[nt][2], sacc[nt][3]);
        }
        __syncthreads();

        // ---- O += P V : 8 k16-steps x 8 n-tiles ----
        #pragma unroll
        for (int ks = 0; ks < 8; ks++) {
            uint32_t af[4];
            ldm_x4(af, Ps_u32 + (offP + ks * 16) * 2);
            #pragma unroll
            for (int ntp = 0; ntp < 4; ntp++) {
                uint32_t tb[4];
                ldm_x4(tb, Vst_u32 + (offV + ntp * 16 * V_P + ks * 16) * 2);
                mma16n8k16(oacc[2 * ntp],     af, &tb[0]);
                mma16n8k16(oacc[2 * ntp + 1], af, &tb[2]);
            }
        }
    }

    // epilogue: normalize, store fp16 concat-ready [B,S,H*D]
    const float inv0 = 1.0f / l0r, inv1 = 1.0f / l1r;
    const int gr0 = q0 + r0l, gr1 = gr0 + 8;
    __half* dst0 = &g_attn[(((size_t)(b * SS + gr0)) * HH + h) * DD];
    __half* dst1 = &g_attn[(((size_t)(b * SS + gr1)) * HH + h) * DD];
    #pragma unroll
    for (int nt = 0; nt < 8; nt++) {
        const int d = nt * 8 + t4 * 2;
        *(__half2*)&dst0[d] = __floats2half2_rn(oacc[nt][0] * inv0, oacc[nt][1] * inv0);
        *(__half2*)&dst1[d] = __floats2half2_rn(oacc[nt][2] * inv1, oacc[nt][3] * inv1);
    }
}

// ============================ host side ============================
extern "C" void kernel_launch(void* const* d_in, const int* in_sizes, int n_in,
                              void* d_out, int out_size)
{
    const float* x  = (const float*)d_in[0];
    const float* Wq = (const float*)d_in[1];
    const float* Wk = (const float*)d_in[2];
    const float* Wv = (const float*)d_in[3];
    const float* bq = (const float*)d_in[4];
    const float* bk = (const float*)d_in[5];
    const float* bv = (const float*)d_in[6];
    const float* Wp = (const float*)d_in[7];
    const float* bp = (const float*)d_in[8];
    float* out = (float*)d_out;
    (void)in_sizes; (void)n_in; (void)out_size;

    cudaFuncSetAttribute(gemm_proj_kernel,
                         cudaFuncAttributeMaxDynamicSharedMemorySize, GSMEM_BYTES);
    cudaFuncSetAttribute(gemm_out_kernel,
                         cudaFuncAttributeMaxDynamicSharedMemorySize, GSMEM_BYTES);
    cudaFuncSetAttribute(attn_mma_kernel,
                         cudaFuncAttributeMaxDynamicSharedMemorySize, ASMEM_BYTES);

    conv_x_kernel<<<1024, 256>>>(x);
    transpose_w_kernel<<<dim3(EE / 32, DD / 32, 48), 256>>>(Wq, Wk, Wv);
    transpose_wp_kernel<<<dim3(EE / 32, EE / 32), 256>>>(Wp);

    gemm_proj_kernel<<<dim3(3 * EE / 128, MTOT / 128), 256, GSMEM_BYTES>>>(bq, bk, bv);

    attn_mma_kernel<<<dim3(SS / 128, HH, BB), 256, ASMEM_BYTES>>>();

    gemm_out_kernel<<<dim3(EE / 128, MTOT / 128), 256, GSMEM_BYTES>>>(bp, out);
}